// round 7
// baseline (speedup 1.0000x reference)
#include <cuda_runtime.h>
#include <cstdint>
#include <math.h>

#define NLY 8
#define Hd 768
#define Ed 1536
#define Nst 16
#define Rr 4
#define Kc 4
#define Cc 3
#define Bb 2
#define Ll 2048
#define Mrows (Bb*Ll)        // 4096
#define DBC (Rr+2*Nst)       // 36
#define TWO_E (2*Ed)         // 3072

typedef signed char s8;

// ======================= scratch (device globals) ============================
__device__ float g_hs  [Mrows*Hd];
__device__ float g_proj[Mrows*TWO_E];
__device__ float g_u   [Mrows*Ed];
__device__ float g_dbc [Mrows*DBC];
__device__ float g_ys  [Mrows*Ed];
__device__ float g_acc [Mrows*Hd];
__device__ float g_yb  [Mrows*Hd];

// int8 activation limbs (reused: x -> ys -> yb -> yb2) + per-row inv scales
__device__ __align__(16) s8 g_aq1[Mrows*Ed];
__device__ __align__(16) s8 g_aq2[Mrows*Ed];
__device__ float g_sa[Mrows];
__device__ __align__(16) s8 g_hq1[Mrows*Hd];
__device__ __align__(16) s8 g_hq2[Mrows*Hd];
__device__ float g_sh[Mrows];

// int8 weight limbs (transposed to [N,K]) + per-out-row inv scales
__device__ __align__(16) s8 g_wiq1[NLY*TWO_E*Hd];
__device__ __align__(16) s8 g_wiq2[NLY*TWO_E*Hd];
__device__ float g_siw[NLY*TWO_E];
__device__ __align__(16) s8 g_woq1[NLY*Hd*Ed];
__device__ __align__(16) s8 g_woq2[NLY*Hd*Ed];
__device__ float g_sow[NLY*Hd];
__device__ __align__(16) s8 g_wfq1[NLY*Cc*Hd*Hd];
__device__ __align__(16) s8 g_wfq2[NLY*Cc*Hd*Hd];
__device__ float g_sfw[NLY*Cc*Hd];

// ======================= helpers =============================================
__device__ __forceinline__ uint32_t smem_u32(const void* p) {
    uint32_t a;
    asm("{ .reg .u64 t; cvta.to.shared.u64 t, %1; cvt.u32.u64 %0, t; }" : "=r"(a) : "l"(p));
    return a;
}
__device__ __forceinline__ void cp_async16(uint32_t dst, const void* src) {
    asm volatile("cp.async.cg.shared.global [%0], [%1], 16;" :: "r"(dst), "l"(src) : "memory");
}
__device__ __forceinline__ void cp_commit() {
    asm volatile("cp.async.commit_group;" ::: "memory");
}
__device__ __forceinline__ void ldm_x4(uint32_t* r, uint32_t addr) {
    asm volatile("ldmatrix.sync.aligned.m8n8.x4.shared.b16 {%0,%1,%2,%3}, [%4];"
                 : "=r"(r[0]), "=r"(r[1]), "=r"(r[2]), "=r"(r[3]) : "r"(addr));
}
__device__ __forceinline__ void mma_s8(int32_t* d, const uint32_t* a, uint32_t b0, uint32_t b1) {
    asm volatile("mma.sync.aligned.m16n8k32.row.col.s32.s8.s8.s32 "
                 "{%0,%1,%2,%3}, {%4,%5,%6,%7}, {%8,%9}, {%0,%1,%2,%3};"
                 : "+r"(d[0]), "+r"(d[1]), "+r"(d[2]), "+r"(d[3])
                 : "r"(a[0]), "r"(a[1]), "r"(a[2]), "r"(a[3]), "r"(b0), "r"(b1));
}
__device__ __forceinline__ void quant2(float v, float s, s8& q1o, s8& q2o) {
    float x = v * s;
    float q1 = rintf(x);
    float r = x - q1;
    q1o = (s8)(int)q1;
    q2o = (s8)(int)rintf(r * 254.f);
}

// ======================= small kernels =======================================
__global__ void embed_kernel(const int* __restrict__ ids, const float* __restrict__ tok,
                             const float* __restrict__ pos, float* __restrict__ hs)
{
    int idx = blockIdx.x*blockDim.x + threadIdx.x;
    if (idx >= Mrows*Hd) return;
    int h = idx % Hd;
    int m = idx / Hd;
    int l = m % Ll;
    int id = ids[m];
    hs[idx] = tok[(size_t)id*Hd + h] + pos[(size_t)l*Hd + h];
}

// LayerNorm (+optional hs += acc/6), output fp32 or int8 2-limb + scale.
template<int HASACC, int OUTQ>
__global__ void ln_fused(float* __restrict__ hs, const float* __restrict__ accv,
                         const float* __restrict__ w, const float* __restrict__ b,
                         float* __restrict__ out32,
                         s8* __restrict__ q1, s8* __restrict__ q2, float* __restrict__ isa)
{
    int row = blockIdx.x;
    size_t base = (size_t)row*Hd;
    int tid = threadIdx.x;
    float v[3];
    float s = 0.f, s2 = 0.f;
    #pragma unroll
    for (int q = 0; q < 3; q++) {
        int i = tid + q*256;
        float t = hs[base + i];
        if (HASACC) { t += (0.5f/3.0f)*accv[base + i]; hs[base + i] = t; }
        v[q] = t;
        s += t; s2 += t*t;
    }
    #pragma unroll
    for (int o = 16; o; o >>= 1) {
        s  += __shfl_xor_sync(0xffffffffu, s,  o);
        s2 += __shfl_xor_sync(0xffffffffu, s2, o);
    }
    __shared__ float sa[8], sb[8], sm[8];
    __shared__ float sh_mean, sh_inv, sh_scale;
    int wi = tid >> 5;
    if ((tid & 31) == 0) { sa[wi] = s; sb[wi] = s2; }
    __syncthreads();
    if (tid == 0) {
        float ts = 0.f, t2 = 0.f;
        #pragma unroll
        for (int i = 0; i < 8; i++) { ts += sa[i]; t2 += sb[i]; }
        float m  = ts / (float)Hd;
        float var = t2 / (float)Hd - m*m;
        sh_mean = m;
        sh_inv  = rsqrtf(var + 1e-5f);
    }
    __syncthreads();
    float mean = sh_mean, inv = sh_inv;
    float y[3];
    float mx = 0.f;
    #pragma unroll
    for (int q = 0; q < 3; q++) {
        int i = tid + q*256;
        y[q] = (v[q] - mean) * inv * w[i] + b[i];
        mx = fmaxf(mx, fabsf(y[q]));
    }
    if (OUTQ) {
        #pragma unroll
        for (int o = 16; o; o >>= 1) mx = fmaxf(mx, __shfl_xor_sync(0xffffffffu, mx, o));
        if ((tid & 31) == 0) sm[wi] = mx;
        __syncthreads();
        if (tid == 0) {
            float m2 = 0.f;
            #pragma unroll
            for (int i = 0; i < 8; i++) m2 = fmaxf(m2, sm[i]);
            sh_scale = 127.f / fmaxf(m2, 1e-20f);
            isa[row] = m2 / 127.f;
        }
        __syncthreads();
        float sc = sh_scale;
        #pragma unroll
        for (int q = 0; q < 3; q++) {
            int i = tid + q*256;
            s8 a, bq;
            quant2(y[q], sc, a, bq);
            q1[base + i] = a;
            q2[base + i] = bq;
        }
    } else {
        #pragma unroll
        for (int q = 0; q < 3; q++) out32[base + tid + q*256] = y[q];
    }
}

// Per-row quantization of an fp32 activation matrix [Mrows, W].
__global__ void quant_rows(const float* __restrict__ x, int W,
                           s8* __restrict__ q1, s8* __restrict__ q2, float* __restrict__ isa)
{
    int row = blockIdx.x;
    size_t base = (size_t)row*W;
    int tid = threadIdx.x;
    float mx = 0.f;
    for (int i = tid; i < W; i += 256) mx = fmaxf(mx, fabsf(x[base + i]));
    #pragma unroll
    for (int o = 16; o; o >>= 1) mx = fmaxf(mx, __shfl_xor_sync(0xffffffffu, mx, o));
    __shared__ float sm[8];
    __shared__ float sh_scale;
    if ((tid & 31) == 0) sm[tid >> 5] = mx;
    __syncthreads();
    if (tid == 0) {
        float m2 = 0.f;
        #pragma unroll
        for (int i = 0; i < 8; i++) m2 = fmaxf(m2, sm[i]);
        sh_scale = 127.f / fmaxf(m2, 1e-20f);
        isa[row] = m2 / 127.f;
    }
    __syncthreads();
    float sc = sh_scale;
    for (int i = tid; i < W; i += 256) {
        s8 a, b;
        quant2(x[base + i], sc, a, b);
        q1[base + i] = a;
        q2[base + i] = b;
    }
}

// Weight quant: W[z][K][N] fp32 -> q1/q2 [z][N][K] int8 + isb[z][N].
__global__ void wquant(const float* __restrict__ W, int K, int N,
                       s8* __restrict__ q1, s8* __restrict__ q2, float* __restrict__ isb)
{
    int n = blockIdx.x, z = blockIdx.y;
    const float* Wz = W + (size_t)z*K*N;
    int tid = threadIdx.x;
    float mx = 0.f;
    for (int k = tid; k < K; k += 256) mx = fmaxf(mx, fabsf(Wz[(size_t)k*N + n]));
    #pragma unroll
    for (int o = 16; o; o >>= 1) mx = fmaxf(mx, __shfl_xor_sync(0xffffffffu, mx, o));
    __shared__ float sm[8];
    __shared__ float sh_scale;
    if ((tid & 31) == 0) sm[tid >> 5] = mx;
    __syncthreads();
    if (tid == 0) {
        float m2 = 0.f;
        #pragma unroll
        for (int i = 0; i < 8; i++) m2 = fmaxf(m2, sm[i]);
        sh_scale = 127.f / fmaxf(m2, 1e-20f);
        isb[(size_t)z*N + n] = m2 / 127.f;
    }
    __syncthreads();
    float sc = sh_scale;
    size_t obase = (size_t)z*N*K + (size_t)n*K;
    for (int k = tid; k < K; k += 256) {
        s8 a, b;
        quant2(Wz[(size_t)k*N + n], sc, a, b);
        q1[obase + k] = a;
        q2[obase + k] = b;
    }
}

// ======================= int8 two-limb GEMM ==================================
// C = act( dequant( (Aq1+Aq2/254)[M,K] @ (Bq1+Bq2/254)[N,K]^T ) + bias [+add] )
// 128x128 CTA tile, BK=64 (int8), 4-stage cp.async, warp tile 64x32.
// stage: A1(8K) A2(8K) B1(8K) B2(8K) = 32KB; 4 stages = 128KB.
#define QSTAGE 32768
#define QSMEM  (4*QSTAGE)

template<int ACT, int ACCU, int HASADD>
__global__ __launch_bounds__(256)
void s8_gemm(const s8* __restrict__ A1, const s8* __restrict__ A2,
             const s8* __restrict__ B1, const s8* __restrict__ B2,
             const float* __restrict__ isa, const float* __restrict__ isb,
             const float* __restrict__ bias, const float* __restrict__ add,
             float* __restrict__ C, int M, int K, int N)
{
    extern __shared__ __align__(16) char smem[];
    const uint32_t sb0 = smem_u32(smem);
    int tid = threadIdx.x, lane = tid & 31, wid = tid >> 5;
    int m0 = blockIdx.y << 7, n0 = blockIdx.x << 7;
    int wm = (wid >> 2) * 64, wn = (wid & 3) * 32;

    const s8* gsrc[4] = { A1 + (size_t)m0*K, A2 + (size_t)m0*K,
                          B1 + (size_t)n0*K, B2 + (size_t)n0*K };

    // copy: per matrix 512 16B-chunks (128 rows x 4 chunks), 2 per thread
    const int r0 = (tid*2) >> 2, c0 = (tid*2) & 3;
    const int r1 = (tid*2+1) >> 2, c1 = (tid*2+1) & 3;
    const uint32_t so0 = (uint32_t)(r0*64 + ((c0 ^ ((r0>>1)&3))<<4));
    const uint32_t so1 = (uint32_t)(r1*64 + ((c1 ^ ((r1>>1)&3))<<4));

    int32_t acc1[4][4][4], acc2[4][4][4];
    #pragma unroll
    for (int t = 0; t < 4; t++)
        #pragma unroll
        for (int j = 0; j < 4; j++)
            #pragma unroll
            for (int e = 0; e < 4; e++) { acc1[t][j][e] = 0; acc2[t][j][e] = 0; }

    const int nk = K >> 6;   // k-tiles of 64 int8

    #pragma unroll
    for (int p = 0; p < 3; p++) {
        uint32_t st = sb0 + p*QSTAGE;
        int k0 = p << 6;
        #pragma unroll
        for (int mat = 0; mat < 4; mat++) {
            const s8* src = gsrc[mat] + k0;
            uint32_t sbase = st + mat*8192u;
            cp_async16(sbase + so0, src + (size_t)r0*K + c0*16);
            cp_async16(sbase + so1, src + (size_t)r1*K + c1*16);
        }
        cp_commit();
    }

    int stage = 0;
    for (int i = 0; i < nk; i++) {
        asm volatile("cp.async.wait_group 2;" ::: "memory");
        __syncthreads();

        uint32_t st = sb0 + stage*QSTAGE;
        int g = lane >> 3;
        int rA = (lane & 7) + (g & 1)*8;
        int kh = g >> 1;

        #pragma unroll
        for (int s = 0; s < 2; s++) {     // two k32 steps per 64B row
            int cch = s*2 + kh;
            uint32_t b1f[2][4], b2f[2][4];
            #pragma unroll
            for (int u = 0; u < 2; u++) {
                int row = wn + u*16 + rA;
                uint32_t off = (uint32_t)(row*64 + ((cch ^ ((row>>1)&3))<<4));
                ldm_x4(b1f[u], st + 16384u + off);
                ldm_x4(b2f[u], st + 24576u + off);
            }
            uint32_t a1f[4][4], a2f[4][4];
            #pragma unroll
            for (int t = 0; t < 4; t++) {
                int row = wm + t*16 + rA;
                uint32_t off = (uint32_t)(row*64 + ((cch ^ ((row>>1)&3))<<4));
                ldm_x4(a1f[t], st + off);
                ldm_x4(a2f[t], st + 8192u + off);
            }
            // q1*q1 -> acc1 (16 independent MMAs)
            #pragma unroll
            for (int t = 0; t < 4; t++)
                #pragma unroll
                for (int j = 0; j < 4; j++) {
                    int u = j >> 1, w = j & 1;
                    mma_s8(acc1[t][j], a1f[t], b1f[u][w], b1f[u][w+2]);
                }
            // q1*q2 -> acc2
            #pragma unroll
            for (int t = 0; t < 4; t++)
                #pragma unroll
                for (int j = 0; j < 4; j++) {
                    int u = j >> 1, w = j & 1;
                    mma_s8(acc2[t][j], a1f[t], b2f[u][w], b2f[u][w+2]);
                }
            // q2*q1 -> acc2
            #pragma unroll
            for (int t = 0; t < 4; t++)
                #pragma unroll
                for (int j = 0; j < 4; j++) {
                    int u = j >> 1, w = j & 1;
                    mma_s8(acc2[t][j], a2f[t], b1f[u][w], b1f[u][w+2]);
                }
        }

        if (i + 3 < nk) {
            uint32_t stp = sb0 + ((stage + 3) & 3)*QSTAGE;
            int k0 = (i + 3) << 6;
            #pragma unroll
            for (int mat = 0; mat < 4; mat++) {
                const s8* src = gsrc[mat] + k0;
                uint32_t sbase = stp + mat*8192u;
                cp_async16(sbase + so0, src + (size_t)r0*K + c0*16);
                cp_async16(sbase + so1, src + (size_t)r1*K + c1*16);
            }
        }
        cp_commit();   // keep group accounting uniform (empty group when no prefetch)
        stage = (stage + 1) & 3;
    }

    // ---- epilogue: dequant + bias + (add) + (silu) + (accumulate) ----
    const float inv254 = 1.f/254.f;
    #pragma unroll
    for (int t = 0; t < 4; t++) {
        int rlo = m0 + wm + t*16 + (lane >> 2);
        float ia[2] = { isa[rlo], isa[rlo + 8] };
        #pragma unroll
        for (int j = 0; j < 4; j++) {
            int col = n0 + wn + j*8 + 2*(lane & 3);
            float ib0 = isb[col], ib1 = isb[col+1];
            float b0 = bias[col], b1 = bias[col+1];
            #pragma unroll
            for (int half = 0; half < 2; half++) {
                int row = rlo + half*8;
                float sc = ia[half];
                float v0 = ((float)acc1[t][j][half*2+0] + (float)acc2[t][j][half*2+0]*inv254)*(sc*ib0) + b0;
                float v1 = ((float)acc1[t][j][half*2+1] + (float)acc2[t][j][half*2+1]*inv254)*(sc*ib1) + b1;
                size_t o = (size_t)row*N + col;
                if (HASADD) { v0 += add[o]; v1 += add[o+1]; }
                if (ACT) {
                    v0 = v0 / (1.f + __expf(-v0));
                    v1 = v1 / (1.f + __expf(-v1));
                }
                if (ACCU) { v0 += C[o]; v1 += C[o+1]; }
                *(float2*)(C + o) = make_float2(v0, v1);
            }
        }
    }
}

// ======================= conv / xproj / scan =================================
__global__ void conv_silu(const float* __restrict__ proj, const float* __restrict__ cw,
                          const float* __restrict__ cb, float* __restrict__ u)
{
    int idx = blockIdx.x*blockDim.x + threadIdx.x;
    if (idx >= Mrows*Ed) return;
    int e = idx % Ed;
    int m = idx / Ed;
    int l = m % Ll;
    float w0 = cw[e*4+0], w1 = cw[e*4+1], w2 = cw[e*4+2], w3 = cw[e*4+3];
    float v = cb[e];
    const float* base = proj + (size_t)m*TWO_E + e;
    if (l >= 3) v += base[-3*TWO_E]*w0;
    if (l >= 2) v += base[-2*TWO_E]*w1;
    if (l >= 1) v += base[-1*TWO_E]*w2;
    v += base[0]*w3;
    u[idx] = v / (1.f + __expf(-v));
}

__global__ __launch_bounds__(256)
void xproj_kernel(const float* __restrict__ u, const float* __restrict__ xw,
                  float* __restrict__ dbc)
{
    __shared__ float sxw[128*37];
    int tid = threadIdx.x, lane = tid & 31, w = tid >> 5;
    int m = blockIdx.x*8 + w;

    float acc[DBC];
    #pragma unroll
    for (int j = 0; j < DBC; j++) acc[j] = 0.f;

    for (int k0 = 0; k0 < Ed; k0 += 128) {
        __syncthreads();
        for (int i = tid; i < 128*DBC; i += 256) {
            int k = i / DBC, j = i - k*DBC;
            sxw[k*37 + j] = xw[(size_t)k0*DBC + i];
        }
        __syncthreads();
        #pragma unroll
        for (int q = 0; q < 4; q++) {
            float uv = u[(size_t)m*Ed + k0 + q*32 + lane];
            const float* row = &sxw[(q*32 + lane)*37];
            #pragma unroll
            for (int j = 0; j < DBC; j++) acc[j] += uv * row[j];
        }
    }
    #pragma unroll
    for (int j = 0; j < DBC; j++) {
        float s = acc[j];
        s += __shfl_xor_sync(0xffffffffu, s, 16);
        s += __shfl_xor_sync(0xffffffffu, s, 8);
        s += __shfl_xor_sync(0xffffffffu, s, 4);
        s += __shfl_xor_sync(0xffffffffu, s, 2);
        s += __shfl_xor_sync(0xffffffffu, s, 1);
        if (lane == 0) dbc[(size_t)m*DBC + j] = s;
    }
}

__global__ void scan_kernel(const float* __restrict__ u, const float* __restrict__ dbc,
                            const float* __restrict__ proj,
                            const float* __restrict__ dt_w, const float* __restrict__ dt_b,
                            const float* __restrict__ A_log, const float* __restrict__ Dv,
                            float* __restrict__ ys)
{
    int gw = (blockIdx.x*blockDim.x + threadIdx.x) >> 5;
    int lane = threadIdx.x & 31;
    int ch = gw*2 + (lane >> 4);
    int b = ch / Ed, e = ch - b*Ed;
    int n = lane & 15;

    float Ac = -__expf(A_log[e*Nst + n]);
    float Dc = Dv[e];
    float w0 = dt_w[e], w1 = dt_w[Ed + e], w2 = dt_w[2*Ed + e], w3 = dt_w[3*Ed + e];
    float dtb = dt_b[e];

    const float* up = u    + (size_t)b*Ll*Ed + e;
    const float* dp = dbc  + (size_t)b*Ll*DBC;
    const float* gp = proj + (size_t)b*Ll*TWO_E + Ed + e;
    float*       yp = ys   + (size_t)b*Ll*Ed + e;

    float h = 0.f;
    for (int t0 = 0; t0 < Ll; t0 += 4) {
        float p[4], uq[4];
        #pragma unroll
        for (int q = 0; q < 4; q++) {
            int t = t0 + q;
            const float* dr = dp + t*DBC;
            float4 d4 = *(const float4*)dr;
            float xdt = d4.x*w0 + d4.y*w1 + d4.z*w2 + d4.w*w3 + dtb;
            float dtv = (xdt > 20.f) ? xdt : log1pf(__expf(xdt));
            float uv = up[(size_t)t*Ed];
            float bt = dr[Rr + n];
            float ct = dr[Rr + Nst + n];
            h = h*__expf(dtv*Ac) + (dtv*uv)*bt;
            p[q] = h*ct;
            uq[q] = uv;
        }
        #pragma unroll
        for (int q = 0; q < 4; q++) {
            p[q] += __shfl_xor_sync(0xffffffffu, p[q], 8);
            p[q] += __shfl_xor_sync(0xffffffffu, p[q], 4);
            p[q] += __shfl_xor_sync(0xffffffffu, p[q], 2);
            p[q] += __shfl_xor_sync(0xffffffffu, p[q], 1);
        }
        if (n == 0) {
            #pragma unroll
            for (int q = 0; q < 4; q++) {
                int t = t0 + q;
                float g = gp[(size_t)t*TWO_E];
                yp[(size_t)t*Ed] = (p[q] + uq[q]*Dc) / (1.f + __expf(-g));
            }
        }
    }
}

// ======================= launch ==============================================
extern "C" void kernel_launch(void* const* d_in, const int* in_sizes, int n_in,
                              void* d_out, int out_size)
{
    const int*   ids     = (const int*)  d_in[0];
    const float* tok_emb = (const float*)d_in[1];
    const float* pos_emb = (const float*)d_in[2];
    const float* ln_w    = (const float*)d_in[3];
    const float* ln_b    = (const float*)d_in[4];
    const float* in_w    = (const float*)d_in[5];
    const float* in_b    = (const float*)d_in[6];
    const float* conv_w  = (const float*)d_in[7];
    const float* conv_b  = (const float*)d_in[8];
    const float* xproj_w = (const float*)d_in[9];
    const float* dt_w    = (const float*)d_in[10];
    const float* dt_b    = (const float*)d_in[11];
    const float* A_log   = (const float*)d_in[12];
    const float* Dv      = (const float*)d_in[13];
    const float* out_w   = (const float*)d_in[14];
    const float* out_b   = (const float*)d_in[15];
    const float* frac_w  = (const float*)d_in[16];
    const float* frac_b  = (const float*)d_in[17];
    const float* fln_w   = (const float*)d_in[18];
    const float* fln_b   = (const float*)d_in[19];

    float *hs, *proj, *u, *dbc, *ys, *acc, *yb;
    float *sa, *sh, *siw, *sow, *sfw;
    s8 *aq1, *aq2, *hq1, *hq2, *wiq1, *wiq2, *woq1, *woq2, *wfq1, *wfq2;
    cudaGetSymbolAddress((void**)&hs,   g_hs);
    cudaGetSymbolAddress((void**)&proj, g_proj);
    cudaGetSymbolAddress((void**)&u,    g_u);
    cudaGetSymbolAddress((void**)&dbc,  g_dbc);
    cudaGetSymbolAddress((void**)&ys,   g_ys);
    cudaGetSymbolAddress((void**)&acc,  g_acc);
    cudaGetSymbolAddress((void**)&yb,   g_yb);
    cudaGetSymbolAddress((void**)&aq1,  g_aq1);
    cudaGetSymbolAddress((void**)&aq2,  g_aq2);
    cudaGetSymbolAddress((void**)&sa,   g_sa);
    cudaGetSymbolAddress((void**)&hq1,  g_hq1);
    cudaGetSymbolAddress((void**)&hq2,  g_hq2);
    cudaGetSymbolAddress((void**)&sh,   g_sh);
    cudaGetSymbolAddress((void**)&wiq1, g_wiq1);
    cudaGetSymbolAddress((void**)&wiq2, g_wiq2);
    cudaGetSymbolAddress((void**)&siw,  g_siw);
    cudaGetSymbolAddress((void**)&woq1, g_woq1);
    cudaGetSymbolAddress((void**)&woq2, g_woq2);
    cudaGetSymbolAddress((void**)&sow,  g_sow);
    cudaGetSymbolAddress((void**)&wfq1, g_wfq1);
    cudaGetSymbolAddress((void**)&wfq2, g_wfq2);
    cudaGetSymbolAddress((void**)&sfw,  g_sfw);

    cudaFuncSetAttribute(s8_gemm<0,0,0>, cudaFuncAttributeMaxDynamicSharedMemorySize, QSMEM);
    cudaFuncSetAttribute(s8_gemm<0,0,1>, cudaFuncAttributeMaxDynamicSharedMemorySize, QSMEM);
    cudaFuncSetAttribute(s8_gemm<1,0,0>, cudaFuncAttributeMaxDynamicSharedMemorySize, QSMEM);
    cudaFuncSetAttribute(s8_gemm<1,1,0>, cudaFuncAttributeMaxDynamicSharedMemorySize, QSMEM);

    // one-time weight quantization (transposed, 2 limbs, per-row scale)
    wquant<<<dim3(TWO_E, NLY), 256>>>(in_w,  Hd, TWO_E, wiq1, wiq2, siw);
    wquant<<<dim3(Hd, NLY),    256>>>(out_w, Ed, Hd,    woq1, woq2, sow);
    wquant<<<dim3(Hd, NLY*Cc), 256>>>(frac_w, Hd, Hd,   wfq1, wfq2, sfw);

    embed_kernel<<<(Mrows*Hd + 255)/256, 256>>>(ids, tok_emb, pos_emb, hs);

    for (int l = 0; l < NLY; l++) {
        // x = LN(hs [+acc/6]) -> int8 limbs
        if (l == 0)
            ln_fused<0,1><<<Mrows, 256>>>(hs, nullptr,
                ln_w + (size_t)l*Hd, ln_b + (size_t)l*Hd, nullptr, aq1, aq2, sa);
        else
            ln_fused<1,1><<<Mrows, 256>>>(hs, acc,
                ln_w + (size_t)l*Hd, ln_b + (size_t)l*Hd, nullptr, aq1, aq2, sa);

        // proj = x @ in_w + in_b
        s8_gemm<0,0,0><<<dim3(TWO_E/128, Mrows/128), 256, QSMEM>>>(
            aq1, aq2, wiq1 + (size_t)l*TWO_E*Hd, wiq2 + (size_t)l*TWO_E*Hd,
            sa, siw + (size_t)l*TWO_E, in_b + (size_t)l*TWO_E, nullptr,
            proj, Mrows, Hd, TWO_E);

        conv_silu<<<(Mrows*Ed + 255)/256, 256>>>(
            proj, conv_w + (size_t)l*Ed*Kc, conv_b + (size_t)l*Ed, u);

        xproj_kernel<<<Mrows/8, 256>>>(u, xproj_w + (size_t)l*Ed*DBC, dbc);

        scan_kernel<<<192, 256>>>(u, dbc, proj,
            dt_w + (size_t)l*Rr*Ed, dt_b + (size_t)l*Ed,
            A_log + (size_t)l*Ed*Nst, Dv + (size_t)l*Ed, ys);

        // hs = ys @ out_w + out_b + hs
        quant_rows<<<Mrows, 256>>>(ys, Ed, aq1, aq2, sa);
        s8_gemm<0,0,1><<<dim3(Hd/128, Mrows/128), 256, QSMEM>>>(
            aq1, aq2, woq1 + (size_t)l*Hd*Ed, woq2 + (size_t)l*Hd*Ed,
            sa, sow + (size_t)l*Hd, out_b + (size_t)l*Hd, hs,
            hs, Mrows, Ed, Hd);

        // fractal: acc = sum_i silu^3(hs)
        quant_rows<<<Mrows, 256>>>(hs, Hd, hq1, hq2, sh);
        for (int i = 0; i < Cc; i++) {
            const s8* fq1 = wfq1 + ((size_t)l*Cc + i)*Hd*Hd;
            const s8* fq2 = wfq2 + ((size_t)l*Cc + i)*Hd*Hd;
            const float* fsb = sfw + ((size_t)l*Cc + i)*Hd;
            const float* fb  = frac_b + ((size_t)l*Cc + i)*Hd;
            s8_gemm<1,0,0><<<dim3(Hd/128, Mrows/128), 256, QSMEM>>>(
                hq1, hq2, fq1, fq2, sh, fsb, fb, nullptr, yb, Mrows, Hd, Hd);
            quant_rows<<<Mrows, 256>>>(yb, Hd, aq1, aq2, sa);
            s8_gemm<1,0,0><<<dim3(Hd/128, Mrows/128), 256, QSMEM>>>(
                aq1, aq2, fq1, fq2, sa, fsb, fb, nullptr, yb, Mrows, Hd, Hd);
            quant_rows<<<Mrows, 256>>>(yb, Hd, aq1, aq2, sa);
            if (i == 0)
                s8_gemm<1,0,0><<<dim3(Hd/128, Mrows/128), 256, QSMEM>>>(
                    aq1, aq2, fq1, fq2, sa, fsb, fb, nullptr, acc, Mrows, Hd, Hd);
            else
                s8_gemm<1,1,0><<<dim3(Hd/128, Mrows/128), 256, QSMEM>>>(
                    aq1, aq2, fq1, fq2, sa, fsb, fb, nullptr, acc, Mrows, Hd, Hd);
        }
    }

    // final: hs += acc/6 ; out = LN(hs)
    ln_fused<1,0><<<Mrows, 256>>>(hs, acc, fln_w, fln_b, (float*)d_out,
                                  nullptr, nullptr, nullptr);
}

// round 8
// speedup vs baseline: 1.9434x; 1.9434x over previous
#include <cuda_runtime.h>
#include <cuda_fp16.h>
#include <cstdint>
#include <math.h>

#define NLY 8
#define Hd 768
#define Ed 1536
#define Nst 16
#define Rr 4
#define Kc 4
#define Cc 3
#define Bb 2
#define Ll 2048
#define Mrows (Bb*Ll)        // 4096
#define DBC (Rr+2*Nst)       // 36
#define TWO_E (2*Ed)         // 3072

// ======================= scratch (device globals) ============================
__device__ float g_hs  [Mrows*Hd];
__device__ float g_proj[Mrows*TWO_E];
__device__ float g_u   [Mrows*Ed];
__device__ float g_dbc [Mrows*DBC];
__device__ float g_acc [Mrows*Hd];

// fp16 weights, transposed to [N,K]
__device__ __align__(16) __half g_wi [NLY*TWO_E*Hd];
__device__ __align__(16) __half g_wo [NLY*Hd*Ed];
__device__ __align__(16) __half g_wf [NLY*Cc*Hd*Hd];
// fp16 activations
__device__ __align__(16) __half g_xq [Mrows*Ed];   // x | ys | yb2
__device__ __align__(16) __half g_hq [Mrows*Hd];   // hs (fp16 copy)
__device__ __align__(16) __half g_ybq[Mrows*Hd];   // yb

// ======================= helpers =============================================
__device__ __forceinline__ uint32_t smem_u32(const void* p) {
    uint32_t a;
    asm("{ .reg .u64 t; cvta.to.shared.u64 t, %1; cvt.u32.u64 %0, t; }" : "=r"(a) : "l"(p));
    return a;
}
__device__ __forceinline__ void cp_async16(uint32_t dst, const void* src) {
    asm volatile("cp.async.cg.shared.global [%0], [%1], 16;" :: "r"(dst), "l"(src) : "memory");
}
__device__ __forceinline__ void cp_commit() {
    asm volatile("cp.async.commit_group;" ::: "memory");
}
__device__ __forceinline__ void ldm_x4(uint32_t* r, uint32_t addr) {
    asm volatile("ldmatrix.sync.aligned.m8n8.x4.shared.b16 {%0,%1,%2,%3}, [%4];"
                 : "=r"(r[0]), "=r"(r[1]), "=r"(r[2]), "=r"(r[3]) : "r"(addr));
}
__device__ __forceinline__ void mma_f16(float* d, const uint32_t* a, uint32_t b0, uint32_t b1) {
    asm volatile("mma.sync.aligned.m16n8k16.row.col.f32.f16.f16.f32 "
                 "{%0,%1,%2,%3}, {%4,%5,%6,%7}, {%8,%9}, {%0,%1,%2,%3};"
                 : "+f"(d[0]), "+f"(d[1]), "+f"(d[2]), "+f"(d[3])
                 : "r"(a[0]), "r"(a[1]), "r"(a[2]), "r"(a[3]), "r"(b0), "r"(b1));
}

// ======================= small kernels =======================================
__global__ void embed_kernel(const int* __restrict__ ids, const float* __restrict__ tok,
                             const float* __restrict__ pos, float* __restrict__ hs)
{
    int idx = blockIdx.x*blockDim.x + threadIdx.x;
    if (idx >= Mrows*Hd) return;
    int h = idx % Hd;
    int m = idx / Hd;
    int l = m % Ll;
    int id = ids[m];
    hs[idx] = tok[(size_t)id*Hd + h] + pos[(size_t)l*Hd + h];
}

// LayerNorm (+optional hs += acc/6); output fp32 or fp16.
template<int HASACC, int OUTH>
__global__ void ln_fused(float* __restrict__ hs, const float* __restrict__ accv,
                         const float* __restrict__ w, const float* __restrict__ b,
                         float* __restrict__ out32, __half* __restrict__ oh)
{
    int row = blockIdx.x;
    size_t base = (size_t)row*Hd;
    int tid = threadIdx.x;
    float v[3];
    float s = 0.f, s2 = 0.f;
    #pragma unroll
    for (int q = 0; q < 3; q++) {
        int i = tid + q*256;
        float t = hs[base + i];
        if (HASACC) { t += (0.5f/3.0f)*accv[base + i]; hs[base + i] = t; }
        v[q] = t;
        s += t; s2 += t*t;
    }
    #pragma unroll
    for (int o = 16; o; o >>= 1) {
        s  += __shfl_xor_sync(0xffffffffu, s,  o);
        s2 += __shfl_xor_sync(0xffffffffu, s2, o);
    }
    __shared__ float sa[8], sb[8];
    __shared__ float sh_mean, sh_inv;
    int wi = tid >> 5;
    if ((tid & 31) == 0) { sa[wi] = s; sb[wi] = s2; }
    __syncthreads();
    if (tid == 0) {
        float ts = 0.f, t2 = 0.f;
        #pragma unroll
        for (int i = 0; i < 8; i++) { ts += sa[i]; t2 += sb[i]; }
        float m  = ts / (float)Hd;
        float var = t2 / (float)Hd - m*m;
        sh_mean = m;
        sh_inv  = rsqrtf(var + 1e-5f);
    }
    __syncthreads();
    float mean = sh_mean, inv = sh_inv;
    #pragma unroll
    for (int q = 0; q < 3; q++) {
        int i = tid + q*256;
        float y = (v[q] - mean) * inv * w[i] + b[i];
        if (OUTH) oh[base + i] = __float2half(y);
        else      out32[base + i] = y;
    }
}

// W[z][K][N] fp32 -> T[z][N][K] fp16
__global__ void wtrans(const float* __restrict__ W, __half* __restrict__ T, int K, int N)
{
    __shared__ float t[32][33];
    size_t moff = (size_t)blockIdx.z * K * N;
    int nx = blockIdx.x*32, kx = blockIdx.y*32;
    int tx = threadIdx.x, ty = threadIdx.y;
    #pragma unroll
    for (int r = 0; r < 32; r += 8)
        t[ty + r][tx] = W[moff + (size_t)(kx + ty + r)*N + nx + tx];
    __syncthreads();
    #pragma unroll
    for (int r = 0; r < 32; r += 8)
        T[moff + (size_t)(nx + ty + r)*K + kx + tx] = __float2half(t[tx][ty + r]);
}

// ======================= fp16 mma GEMM =======================================
// C = act( A[M,K] @ B[N,K]^T + bias [+add] ),  A,B fp16 K-major.
// 128x128 CTA tile, BK=32, 3-stage cp.async, warp tile 64x32, 2 CTAs/SM.
// stage: A(8K) B(8K) = 16KB; 3 stages = 48KB.
#define HSTAGE 16384
#define HSMEM  (3*HSTAGE)

template<int ACT, int ACCU, int HASADD, int OUTF32, int OUTH>
__global__ __launch_bounds__(256, 2)
void h_gemm(const __half* __restrict__ A, const __half* __restrict__ B,
            const float* __restrict__ bias, const float* __restrict__ add,
            float* __restrict__ C, __half* __restrict__ Oh, int M, int K, int N)
{
    extern __shared__ __align__(16) char smem[];
    const uint32_t sb0 = smem_u32(smem);
    int tid = threadIdx.x, lane = tid & 31, wid = tid >> 5;
    int m0 = blockIdx.y << 7, n0 = blockIdx.x << 7;
    int wm = (wid >> 2) * 64, wn = (wid & 3) * 32;

    const __half* gsrc[2] = { A + (size_t)m0*K, B + (size_t)n0*K };

    // per matrix: 128 rows x 4 16B-chunks = 512 chunks; 2 per thread
    const int r0 = (tid*2) >> 2, c0 = (tid*2) & 3;
    const int r1 = (tid*2+1) >> 2, c1 = (tid*2+1) & 3;
    const uint32_t so0 = (uint32_t)(r0*64 + ((c0 ^ ((r0>>1)&3))<<4));
    const uint32_t so1 = (uint32_t)(r1*64 + ((c1 ^ ((r1>>1)&3))<<4));

    float acc[4][4][4];
    #pragma unroll
    for (int t = 0; t < 4; t++)
        #pragma unroll
        for (int j = 0; j < 4; j++)
            #pragma unroll
            for (int e = 0; e < 4; e++) acc[t][j][e] = 0.f;

    const int nt = K >> 5;

    #pragma unroll
    for (int p = 0; p < 2; p++) {
        uint32_t st = sb0 + p*HSTAGE;
        int k0 = p << 5;
        #pragma unroll
        for (int mat = 0; mat < 2; mat++) {
            const char* src = (const char*)(gsrc[mat] + k0);
            uint32_t sbase = st + mat*8192u;
            cp_async16(sbase + so0, src + (size_t)r0*K*2 + c0*16);
            cp_async16(sbase + so1, src + (size_t)r1*K*2 + c1*16);
        }
        cp_commit();
    }

    int stage = 0, pstage = 2;
    for (int i = 0; i < nt; i++) {
        if (i == nt - 1) asm volatile("cp.async.wait_group 0;" ::: "memory");
        else             asm volatile("cp.async.wait_group 1;" ::: "memory");
        __syncthreads();

        uint32_t st = sb0 + stage*HSTAGE;
        int g = lane >> 3;
        int rA = (lane & 7) + (g & 1)*8;
        int kh = g >> 1;

        #pragma unroll
        for (int s = 0; s < 2; s++) {
            int cch = s*2 + kh;
            uint32_t bf[2][4];
            #pragma unroll
            for (int u = 0; u < 2; u++) {
                int row = wn + u*16 + rA;
                uint32_t off = (uint32_t)(row*64 + ((cch ^ ((row>>1)&3))<<4));
                ldm_x4(bf[u], st + 8192u + off);
            }
            #pragma unroll
            for (int t = 0; t < 4; t++) {
                int row = wm + t*16 + rA;
                uint32_t off = (uint32_t)(row*64 + ((cch ^ ((row>>1)&3))<<4));
                uint32_t af[4];
                ldm_x4(af, st + off);
                #pragma unroll
                for (int j = 0; j < 4; j++) {
                    int u = j >> 1, w = j & 1;
                    mma_f16(acc[t][j], af, bf[u][w], bf[u][w+2]);
                }
            }
        }

        if (i + 2 < nt) {
            uint32_t stp = sb0 + pstage*HSTAGE;
            int k0 = (i + 2) << 5;
            #pragma unroll
            for (int mat = 0; mat < 2; mat++) {
                const char* src = (const char*)(gsrc[mat] + k0);
                uint32_t sbase = stp + mat*8192u;
                cp_async16(sbase + so0, src + (size_t)r0*K*2 + c0*16);
                cp_async16(sbase + so1, src + (size_t)r1*K*2 + c1*16);
            }
            cp_commit();
        }
        stage = (stage + 1 == 3) ? 0 : stage + 1;
        pstage = (pstage + 1 == 3) ? 0 : pstage + 1;
    }

    // ---- epilogue ----
    #pragma unroll
    for (int t = 0; t < 4; t++) {
        int mrow = m0 + wm + t*16 + (lane >> 2);
        #pragma unroll
        for (int j = 0; j < 4; j++) {
            int col = n0 + wn + j*8 + 2*(lane & 3);
            float b0 = bias[col], b1 = bias[col+1];
            #pragma unroll
            for (int half = 0; half < 2; half++) {
                int row = mrow + half*8;
                float v0 = acc[t][j][half*2+0] + b0;
                float v1 = acc[t][j][half*2+1] + b1;
                size_t o = (size_t)row*N + col;
                if (HASADD) { v0 += add[o]; v1 += add[o+1]; }
                if (ACT) {
                    v0 = v0 / (1.f + __expf(-v0));
                    v1 = v1 / (1.f + __expf(-v1));
                }
                if (OUTF32) {
                    if (ACCU) { v0 += C[o]; v1 += C[o+1]; }
                    *(float2*)(C + o) = make_float2(v0, v1);
                }
                if (OUTH) {
                    __half2 hh;
                    hh.x = __float2half(v0);
                    hh.y = __float2half(v1);
                    *(__half2*)(Oh + o) = hh;
                }
            }
        }
    }
}

// ======================= conv / xproj / scan =================================
__global__ void conv_silu(const float* __restrict__ proj, const float* __restrict__ cw,
                          const float* __restrict__ cb, float* __restrict__ u)
{
    int idx = blockIdx.x*blockDim.x + threadIdx.x;
    if (idx >= Mrows*Ed) return;
    int e = idx % Ed;
    int m = idx / Ed;
    int l = m % Ll;
    float w0 = cw[e*4+0], w1 = cw[e*4+1], w2 = cw[e*4+2], w3 = cw[e*4+3];
    float v = cb[e];
    const float* base = proj + (size_t)m*TWO_E + e;
    if (l >= 3) v += base[-3*TWO_E]*w0;
    if (l >= 2) v += base[-2*TWO_E]*w1;
    if (l >= 1) v += base[-1*TWO_E]*w2;
    v += base[0]*w3;
    u[idx] = v / (1.f + __expf(-v));
}

__global__ __launch_bounds__(256)
void xproj_kernel(const float* __restrict__ u, const float* __restrict__ xw,
                  float* __restrict__ dbc)
{
    __shared__ float sxw[128*37];
    int tid = threadIdx.x, lane = tid & 31, w = tid >> 5;
    int m = blockIdx.x*8 + w;

    float acc[DBC];
    #pragma unroll
    for (int j = 0; j < DBC; j++) acc[j] = 0.f;

    for (int k0 = 0; k0 < Ed; k0 += 128) {
        __syncthreads();
        for (int i = tid; i < 128*DBC; i += 256) {
            int k = i / DBC, j = i - k*DBC;
            sxw[k*37 + j] = xw[(size_t)k0*DBC + i];
        }
        __syncthreads();
        #pragma unroll
        for (int q = 0; q < 4; q++) {
            float uv = u[(size_t)m*Ed + k0 + q*32 + lane];
            const float* row = &sxw[(q*32 + lane)*37];
            #pragma unroll
            for (int j = 0; j < DBC; j++) acc[j] += uv * row[j];
        }
    }
    #pragma unroll
    for (int j = 0; j < DBC; j++) {
        float s = acc[j];
        s += __shfl_xor_sync(0xffffffffu, s, 16);
        s += __shfl_xor_sync(0xffffffffu, s, 8);
        s += __shfl_xor_sync(0xffffffffu, s, 4);
        s += __shfl_xor_sync(0xffffffffu, s, 2);
        s += __shfl_xor_sync(0xffffffffu, s, 1);
        if (lane == 0) dbc[(size_t)m*DBC + j] = s;
    }
}

// Selective scan; ys emitted as fp16.
__global__ void scan_kernel(const float* __restrict__ u, const float* __restrict__ dbc,
                            const float* __restrict__ proj,
                            const float* __restrict__ dt_w, const float* __restrict__ dt_b,
                            const float* __restrict__ A_log, const float* __restrict__ Dv,
                            __half* __restrict__ ys)
{
    int gw = (blockIdx.x*blockDim.x + threadIdx.x) >> 5;
    int lane = threadIdx.x & 31;
    int ch = gw*2 + (lane >> 4);
    int b = ch / Ed, e = ch - b*Ed;
    int n = lane & 15;

    float Ac = -__expf(A_log[e*Nst + n]);
    float Dc = Dv[e];
    float w0 = dt_w[e], w1 = dt_w[Ed + e], w2 = dt_w[2*Ed + e], w3 = dt_w[3*Ed + e];
    float dtb = dt_b[e];

    const float* up = u    + (size_t)b*Ll*Ed + e;
    const float* dp = dbc  + (size_t)b*Ll*DBC;
    const float* gp = proj + (size_t)b*Ll*TWO_E + Ed + e;
    size_t ybase = (size_t)b*Ll*Ed + e;

    float h = 0.f;
    for (int t0 = 0; t0 < Ll; t0 += 4) {
        float p[4], uq[4];
        #pragma unroll
        for (int q = 0; q < 4; q++) {
            int t = t0 + q;
            const float* dr = dp + t*DBC;
            float4 d4 = *(const float4*)dr;
            float xdt = d4.x*w0 + d4.y*w1 + d4.z*w2 + d4.w*w3 + dtb;
            float dtv = (xdt > 20.f) ? xdt : log1pf(__expf(xdt));
            float uv = up[(size_t)t*Ed];
            float bt = dr[Rr + n];
            float ct = dr[Rr + Nst + n];
            h = h*__expf(dtv*Ac) + (dtv*uv)*bt;
            p[q] = h*ct;
            uq[q] = uv;
        }
        #pragma unroll
        for (int q = 0; q < 4; q++) {
            p[q] += __shfl_xor_sync(0xffffffffu, p[q], 8);
            p[q] += __shfl_xor_sync(0xffffffffu, p[q], 4);
            p[q] += __shfl_xor_sync(0xffffffffu, p[q], 2);
            p[q] += __shfl_xor_sync(0xffffffffu, p[q], 1);
        }
        if (n == 0) {
            #pragma unroll
            for (int q = 0; q < 4; q++) {
                int t = t0 + q;
                float g = gp[(size_t)t*TWO_E];
                float y = (p[q] + uq[q]*Dc) / (1.f + __expf(-g));
                ys[ybase + (size_t)t*Ed] = __float2half(y);
            }
        }
    }
}

// ======================= launch ==============================================
extern "C" void kernel_launch(void* const* d_in, const int* in_sizes, int n_in,
                              void* d_out, int out_size)
{
    const int*   ids     = (const int*)  d_in[0];
    const float* tok_emb = (const float*)d_in[1];
    const float* pos_emb = (const float*)d_in[2];
    const float* ln_w    = (const float*)d_in[3];
    const float* ln_b    = (const float*)d_in[4];
    const float* in_w    = (const float*)d_in[5];
    const float* in_b    = (const float*)d_in[6];
    const float* conv_w  = (const float*)d_in[7];
    const float* conv_b  = (const float*)d_in[8];
    const float* xproj_w = (const float*)d_in[9];
    const float* dt_w    = (const float*)d_in[10];
    const float* dt_b    = (const float*)d_in[11];
    const float* A_log   = (const float*)d_in[12];
    const float* Dv      = (const float*)d_in[13];
    const float* out_w   = (const float*)d_in[14];
    const float* out_b   = (const float*)d_in[15];
    const float* frac_w  = (const float*)d_in[16];
    const float* frac_b  = (const float*)d_in[17];
    const float* fln_w   = (const float*)d_in[18];
    const float* fln_b   = (const float*)d_in[19];

    float *hs, *proj, *u, *dbc, *acc;
    __half *wi, *wo, *wf, *xq, *hq, *ybq;
    cudaGetSymbolAddress((void**)&hs,   g_hs);
    cudaGetSymbolAddress((void**)&proj, g_proj);
    cudaGetSymbolAddress((void**)&u,    g_u);
    cudaGetSymbolAddress((void**)&dbc,  g_dbc);
    cudaGetSymbolAddress((void**)&acc,  g_acc);
    cudaGetSymbolAddress((void**)&wi,   g_wi);
    cudaGetSymbolAddress((void**)&wo,   g_wo);
    cudaGetSymbolAddress((void**)&wf,   g_wf);
    cudaGetSymbolAddress((void**)&xq,   g_xq);
    cudaGetSymbolAddress((void**)&hq,   g_hq);
    cudaGetSymbolAddress((void**)&ybq,  g_ybq);

    cudaFuncSetAttribute(h_gemm<0,0,0,1,0>, cudaFuncAttributeMaxDynamicSharedMemorySize, HSMEM);
    cudaFuncSetAttribute(h_gemm<0,0,1,1,1>, cudaFuncAttributeMaxDynamicSharedMemorySize, HSMEM);
    cudaFuncSetAttribute(h_gemm<1,0,0,0,1>, cudaFuncAttributeMaxDynamicSharedMemorySize, HSMEM);
    cudaFuncSetAttribute(h_gemm<1,0,0,1,0>, cudaFuncAttributeMaxDynamicSharedMemorySize, HSMEM);
    cudaFuncSetAttribute(h_gemm<1,1,0,1,0>, cudaFuncAttributeMaxDynamicSharedMemorySize, HSMEM);

    // weight transpose -> fp16 [N,K]
    wtrans<<<dim3(TWO_E/32, Hd/32, NLY), dim3(32,8)>>>(in_w, wi, Hd, TWO_E);
    wtrans<<<dim3(Hd/32, Ed/32, NLY),    dim3(32,8)>>>(out_w, wo, Ed, Hd);
    wtrans<<<dim3(Hd/32, Hd/32, NLY*Cc), dim3(32,8)>>>(frac_w, wf, Hd, Hd);

    embed_kernel<<<(Mrows*Hd + 255)/256, 256>>>(ids, tok_emb, pos_emb, hs);

    for (int l = 0; l < NLY; l++) {
        // x = LN(hs [+acc/6]) -> fp16
        if (l == 0)
            ln_fused<0,1><<<Mrows, 256>>>(hs, nullptr,
                ln_w + (size_t)l*Hd, ln_b + (size_t)l*Hd, nullptr, xq);
        else
            ln_fused<1,1><<<Mrows, 256>>>(hs, acc,
                ln_w + (size_t)l*Hd, ln_b + (size_t)l*Hd, nullptr, xq);

        // proj = x @ in_w + in_b (fp32)
        h_gemm<0,0,0,1,0><<<dim3(TWO_E/128, Mrows/128), 256, HSMEM>>>(
            xq, wi + (size_t)l*TWO_E*Hd, in_b + (size_t)l*TWO_E, nullptr,
            proj, nullptr, Mrows, Hd, TWO_E);

        conv_silu<<<(Mrows*Ed + 255)/256, 256>>>(
            proj, conv_w + (size_t)l*Ed*Kc, conv_b + (size_t)l*Ed, u);

        xproj_kernel<<<Mrows/8, 256>>>(u, xproj_w + (size_t)l*Ed*DBC, dbc);

        // scan -> ys fp16 (into xq)
        scan_kernel<<<192, 256>>>(u, dbc, proj,
            dt_w + (size_t)l*Rr*Ed, dt_b + (size_t)l*Ed,
            A_log + (size_t)l*Ed*Nst, Dv + (size_t)l*Ed, xq);

        // hs = ys @ out_w + out_b + hs (fp32) ; also hq = fp16(hs)
        h_gemm<0,0,1,1,1><<<dim3(Hd/128, Mrows/128), 256, HSMEM>>>(
            xq, wo + (size_t)l*Hd*Ed, out_b + (size_t)l*Hd, hs,
            hs, hq, Mrows, Ed, Hd);

        // fractal: acc = sum_i silu^3(hs)
        for (int i = 0; i < Cc; i++) {
            const __half* fw = wf + ((size_t)l*Cc + i)*Hd*Hd;
            const float* fb = frac_b + ((size_t)l*Cc + i)*Hd;
            h_gemm<1,0,0,0,1><<<dim3(Hd/128, Mrows/128), 256, HSMEM>>>(
                hq, fw, fb, nullptr, nullptr, ybq, Mrows, Hd, Hd);
            h_gemm<1,0,0,0,1><<<dim3(Hd/128, Mrows/128), 256, HSMEM>>>(
                ybq, fw, fb, nullptr, nullptr, xq, Mrows, Hd, Hd);
            if (i == 0)
                h_gemm<1,0,0,1,0><<<dim3(Hd/128, Mrows/128), 256, HSMEM>>>(
                    xq, fw, fb, nullptr, acc, nullptr, Mrows, Hd, Hd);
            else
                h_gemm<1,1,0,1,0><<<dim3(Hd/128, Mrows/128), 256, HSMEM>>>(
                    xq, fw, fb, nullptr, acc, nullptr, Mrows, Hd, Hd);
        }
    }

    // final: hs += acc/6 ; out = LN(hs)
    ln_fused<1,0><<<Mrows, 256>>>(hs, acc, fln_w, fln_b, (float*)d_out, nullptr);
}

// round 9
// speedup vs baseline: 2.0536x; 1.0567x over previous
#include <cuda_runtime.h>
#include <cuda_fp16.h>
#include <cstdint>
#include <math.h>

#define NLY 8
#define Hd 768
#define Ed 1536
#define Nst 16
#define Rr 4
#define Kc 4
#define Cc 3
#define Bb 2
#define Ll 2048
#define Mrows (Bb*Ll)        // 4096
#define DBC (Rr+2*Nst)       // 36
#define TWO_E (2*Ed)         // 3072

// ======================= scratch (device globals) ============================
__device__ float g_hs  [Mrows*Hd];
__device__ float g_proj[Mrows*TWO_E];
__device__ float g_u   [Mrows*Ed];
__device__ float g_dbc [Mrows*DBC];
__device__ float g_acc [Mrows*Hd];

// fp16 weights, transposed to [N,K]
__device__ __align__(16) __half g_wi [NLY*TWO_E*Hd];
__device__ __align__(16) __half g_wo [NLY*Hd*Ed];
__device__ __align__(16) __half g_wf [NLY*Cc*Hd*Hd];
// fp16 activations
__device__ __align__(16) __half g_xq [Mrows*Ed];   // x | ys | yb2
__device__ __align__(16) __half g_hq [Mrows*Hd];   // hs (fp16 copy)
__device__ __align__(16) __half g_ybq[Mrows*Hd];   // yb

// ======================= helpers =============================================
__device__ __forceinline__ uint32_t smem_u32(const void* p) {
    uint32_t a;
    asm("{ .reg .u64 t; cvta.to.shared.u64 t, %1; cvt.u32.u64 %0, t; }" : "=r"(a) : "l"(p));
    return a;
}
__device__ __forceinline__ void cp_async16(uint32_t dst, const void* src) {
    asm volatile("cp.async.cg.shared.global [%0], [%1], 16;" :: "r"(dst), "l"(src) : "memory");
}
__device__ __forceinline__ void cp_commit() {
    asm volatile("cp.async.commit_group;" ::: "memory");
}
__device__ __forceinline__ void ldm_x4(uint32_t* r, uint32_t addr) {
    asm volatile("ldmatrix.sync.aligned.m8n8.x4.shared.b16 {%0,%1,%2,%3}, [%4];"
                 : "=r"(r[0]), "=r"(r[1]), "=r"(r[2]), "=r"(r[3]) : "r"(addr));
}
__device__ __forceinline__ void mma_f16(float* d, const uint32_t* a, uint32_t b0, uint32_t b1) {
    asm volatile("mma.sync.aligned.m16n8k16.row.col.f32.f16.f16.f32 "
                 "{%0,%1,%2,%3}, {%4,%5,%6,%7}, {%8,%9}, {%0,%1,%2,%3};"
                 : "+f"(d[0]), "+f"(d[1]), "+f"(d[2]), "+f"(d[3])
                 : "r"(a[0]), "r"(a[1]), "r"(a[2]), "r"(a[3]), "r"(b0), "r"(b1));
}

// ======================= small kernels =======================================
__global__ void embed_kernel(const int* __restrict__ ids, const float* __restrict__ tok,
                             const float* __restrict__ pos, float* __restrict__ hs)
{
    int idx = blockIdx.x*blockDim.x + threadIdx.x;
    if (idx >= Mrows*Hd) return;
    int h = idx % Hd;
    int m = idx / Hd;
    int l = m % Ll;
    int id = ids[m];
    hs[idx] = tok[(size_t)id*Hd + h] + pos[(size_t)l*Hd + h];
}

// LayerNorm (+optional hs += acc/6); output fp32 or fp16.
template<int HASACC, int OUTH>
__global__ void ln_fused(float* __restrict__ hs, const float* __restrict__ accv,
                         const float* __restrict__ w, const float* __restrict__ b,
                         float* __restrict__ out32, __half* __restrict__ oh)
{
    int row = blockIdx.x;
    size_t base = (size_t)row*Hd;
    int tid = threadIdx.x;
    float v[3];
    float s = 0.f, s2 = 0.f;
    #pragma unroll
    for (int q = 0; q < 3; q++) {
        int i = tid + q*256;
        float t = hs[base + i];
        if (HASACC) { t += (0.5f/3.0f)*accv[base + i]; hs[base + i] = t; }
        v[q] = t;
        s += t; s2 += t*t;
    }
    #pragma unroll
    for (int o = 16; o; o >>= 1) {
        s  += __shfl_xor_sync(0xffffffffu, s,  o);
        s2 += __shfl_xor_sync(0xffffffffu, s2, o);
    }
    __shared__ float sa[8], sb[8];
    __shared__ float sh_mean, sh_inv;
    int wi = tid >> 5;
    if ((tid & 31) == 0) { sa[wi] = s; sb[wi] = s2; }
    __syncthreads();
    if (tid == 0) {
        float ts = 0.f, t2 = 0.f;
        #pragma unroll
        for (int i = 0; i < 8; i++) { ts += sa[i]; t2 += sb[i]; }
        float m  = ts / (float)Hd;
        float var = t2 / (float)Hd - m*m;
        sh_mean = m;
        sh_inv  = rsqrtf(var + 1e-5f);
    }
    __syncthreads();
    float mean = sh_mean, inv = sh_inv;
    #pragma unroll
    for (int q = 0; q < 3; q++) {
        int i = tid + q*256;
        float y = (v[q] - mean) * inv * w[i] + b[i];
        if (OUTH) oh[base + i] = __float2half(y);
        else      out32[base + i] = y;
    }
}

// W[z][K][N] fp32 -> T[z][N][K] fp16
__global__ void wtrans(const float* __restrict__ W, __half* __restrict__ T, int K, int N)
{
    __shared__ float t[32][33];
    size_t moff = (size_t)blockIdx.z * K * N;
    int nx = blockIdx.x*32, kx = blockIdx.y*32;
    int tx = threadIdx.x, ty = threadIdx.y;
    #pragma unroll
    for (int r = 0; r < 32; r += 8)
        t[ty + r][tx] = W[moff + (size_t)(kx + ty + r)*N + nx + tx];
    __syncthreads();
    #pragma unroll
    for (int r = 0; r < 32; r += 8)
        T[moff + (size_t)(nx + ty + r)*K + kx + tx] = __float2half(t[tx][ty + r]);
}

// ======================= fp16 mma GEMM (fat warp tiles) ======================
// C = act( A[M,K] @ B[N,K]^T + bias [+add] ),  A,B fp16 K-major.
// CTA tile 128x128, BK=64 (128B smem rows), 4 warps (64x64 each), 128 threads,
// 3-stage cp.async, 2 CTAs/SM.  stage: A(16K) B(16K) = 32KB; 3 stages = 96KB.
#define HSTAGE 32768
#define HSMEM  (3*HSTAGE)

template<int ACT, int ACCU, int HASADD, int OUTF32, int OUTH>
__global__ __launch_bounds__(128, 2)
void h_gemm(const __half* __restrict__ A, const __half* __restrict__ B,
            const float* __restrict__ bias, const float* __restrict__ add,
            float* __restrict__ C, __half* __restrict__ Oh, int M, int K, int N)
{
    extern __shared__ __align__(16) char smem[];
    const uint32_t sb0 = smem_u32(smem);
    int tid = threadIdx.x, lane = tid & 31, wid = tid >> 5;
    int m0 = blockIdx.y << 7, n0 = blockIdx.x << 7;
    int wm = (wid >> 1) * 64, wn = (wid & 1) * 64;

    const __half* gsrc[2] = { A + (size_t)m0*K, B + (size_t)n0*K };

    // copy geometry: 128 rows x 8 16B-chunks per matrix; fixed chunk per thread
    const int cr0 = tid >> 3;            // base row 0..15
    const int cch = tid & 7;             // global 16B chunk
    const int csw = cch ^ (cr0 & 7);     // swizzled chunk (row&7 == cr0&7 for all q)
    const uint32_t cso = (uint32_t)(cr0*128 + csw*16);

    float acc[4][8][4];
    #pragma unroll
    for (int t = 0; t < 4; t++)
        #pragma unroll
        for (int j = 0; j < 8; j++)
            #pragma unroll
            for (int e = 0; e < 4; e++) acc[t][j][e] = 0.f;

    const int nt = K >> 6;

    #pragma unroll
    for (int p = 0; p < 2; p++) {
        uint32_t st = sb0 + p*HSTAGE;
        int k0 = p << 6;
        #pragma unroll
        for (int mat = 0; mat < 2; mat++) {
            const __half* src = gsrc[mat] + k0;
            uint32_t sbase = st + mat*16384u;
            #pragma unroll
            for (int q = 0; q < 8; q++) {
                int row = q*16 + cr0;
                cp_async16(sbase + cso + (uint32_t)(q*2048),
                           src + (size_t)row*K + cch*8);
            }
        }
        cp_commit();
    }

    // ldmatrix lane geometry
    int rA = (lane & 7) + ((lane >> 3) & 1)*8;   // row within 16-tile
    int hi = lane >> 4;                          // 16B half within 32B k16 col

    int stage = 0, pstage = 2;
    for (int i = 0; i < nt; i++) {
        if (i == nt - 1) asm volatile("cp.async.wait_group 0;" ::: "memory");
        else             asm volatile("cp.async.wait_group 1;" ::: "memory");
        __syncthreads();

        uint32_t stA = sb0 + stage*HSTAGE;
        uint32_t stB = stA + 16384u;

        #pragma unroll
        for (int s = 0; s < 4; s++) {            // four k16 phases per k64 tile
            int ck = 2*s + hi;                   // 16B chunk index for this lane
            uint32_t bf[4][4];
            #pragma unroll
            for (int u = 0; u < 4; u++) {
                int row = wn + u*16 + rA;
                uint32_t off = (uint32_t)(row*128 + ((ck ^ (row & 7))<<4));
                ldm_x4(bf[u], stB + off);
            }
            #pragma unroll
            for (int t = 0; t < 4; t++) {
                int row = wm + t*16 + rA;
                uint32_t off = (uint32_t)(row*128 + ((ck ^ (row & 7))<<4));
                uint32_t af[4];
                ldm_x4(af, stA + off);
                #pragma unroll
                for (int j = 0; j < 8; j++) {
                    int u = j >> 1, w = j & 1;
                    mma_f16(acc[t][j], af, bf[u][w], bf[u][w+2]);
                }
            }
        }

        if (i + 2 < nt) {
            uint32_t stp = sb0 + pstage*HSTAGE;
            int k0 = (i + 2) << 6;
            #pragma unroll
            for (int mat = 0; mat < 2; mat++) {
                const __half* src = gsrc[mat] + k0;
                uint32_t sbase = stp + mat*16384u;
                #pragma unroll
                for (int q = 0; q < 8; q++) {
                    int row = q*16 + cr0;
                    cp_async16(sbase + cso + (uint32_t)(q*2048),
                               src + (size_t)row*K + cch*8);
                }
            }
            cp_commit();
        }
        stage = (stage + 1 == 3) ? 0 : stage + 1;
        pstage = (pstage + 1 == 3) ? 0 : pstage + 1;
    }

    // ---- epilogue ----
    #pragma unroll
    for (int t = 0; t < 4; t++) {
        int mrow = m0 + wm + t*16 + (lane >> 2);
        #pragma unroll
        for (int j = 0; j < 8; j++) {
            int col = n0 + wn + j*8 + 2*(lane & 3);
            float b0 = bias[col], b1 = bias[col+1];
            #pragma unroll
            for (int half = 0; half < 2; half++) {
                int row = mrow + half*8;
                float v0 = acc[t][j][half*2+0] + b0;
                float v1 = acc[t][j][half*2+1] + b1;
                size_t o = (size_t)row*N + col;
                if (HASADD) { v0 += add[o]; v1 += add[o+1]; }
                if (ACT) {
                    v0 = v0 / (1.f + __expf(-v0));
                    v1 = v1 / (1.f + __expf(-v1));
                }
                if (OUTF32) {
                    if (ACCU) { v0 += C[o]; v1 += C[o+1]; }
                    *(float2*)(C + o) = make_float2(v0, v1);
                }
                if (OUTH) {
                    __half2 hh;
                    hh.x = __float2half(v0);
                    hh.y = __float2half(v1);
                    *(__half2*)(Oh + o) = hh;
                }
            }
        }
    }
}

// ======================= conv / xproj / scan =================================
__global__ void conv_silu(const float* __restrict__ proj, const float* __restrict__ cw,
                          const float* __restrict__ cb, float* __restrict__ u)
{
    int idx = blockIdx.x*blockDim.x + threadIdx.x;
    if (idx >= Mrows*Ed) return;
    int e = idx % Ed;
    int m = idx / Ed;
    int l = m % Ll;
    float w0 = cw[e*4+0], w1 = cw[e*4+1], w2 = cw[e*4+2], w3 = cw[e*4+3];
    float v = cb[e];
    const float* base = proj + (size_t)m*TWO_E + e;
    if (l >= 3) v += base[-3*TWO_E]*w0;
    if (l >= 2) v += base[-2*TWO_E]*w1;
    if (l >= 1) v += base[-1*TWO_E]*w2;
    v += base[0]*w3;
    u[idx] = v / (1.f + __expf(-v));
}

__global__ __launch_bounds__(256)
void xproj_kernel(const float* __restrict__ u, const float* __restrict__ xw,
                  float* __restrict__ dbc)
{
    __shared__ float sxw[128*37];
    int tid = threadIdx.x, lane = tid & 31, w = tid >> 5;
    int m = blockIdx.x*8 + w;

    float acc[DBC];
    #pragma unroll
    for (int j = 0; j < DBC; j++) acc[j] = 0.f;

    for (int k0 = 0; k0 < Ed; k0 += 128) {
        __syncthreads();
        for (int i = tid; i < 128*DBC; i += 256) {
            int k = i / DBC, j = i - k*DBC;
            sxw[k*37 + j] = xw[(size_t)k0*DBC + i];
        }
        __syncthreads();
        #pragma unroll
        for (int q = 0; q < 4; q++) {
            float uv = u[(size_t)m*Ed + k0 + q*32 + lane];
            const float* row = &sxw[(q*32 + lane)*37];
            #pragma unroll
            for (int j = 0; j < DBC; j++) acc[j] += uv * row[j];
        }
    }
    #pragma unroll
    for (int j = 0; j < DBC; j++) {
        float s = acc[j];
        s += __shfl_xor_sync(0xffffffffu, s, 16);
        s += __shfl_xor_sync(0xffffffffu, s, 8);
        s += __shfl_xor_sync(0xffffffffu, s, 4);
        s += __shfl_xor_sync(0xffffffffu, s, 2);
        s += __shfl_xor_sync(0xffffffffu, s, 1);
        if (lane == 0) dbc[(size_t)m*DBC + j] = s;
    }
}

// Selective scan; ys emitted as fp16.
__global__ void scan_kernel(const float* __restrict__ u, const float* __restrict__ dbc,
                            const float* __restrict__ proj,
                            const float* __restrict__ dt_w, const float* __restrict__ dt_b,
                            const float* __restrict__ A_log, const float* __restrict__ Dv,
                            __half* __restrict__ ys)
{
    int gw = (blockIdx.x*blockDim.x + threadIdx.x) >> 5;
    int lane = threadIdx.x & 31;
    int ch = gw*2 + (lane >> 4);
    int b = ch / Ed, e = ch - b*Ed;
    int n = lane & 15;

    float Ac = -__expf(A_log[e*Nst + n]);
    float Dc = Dv[e];
    float w0 = dt_w[e], w1 = dt_w[Ed + e], w2 = dt_w[2*Ed + e], w3 = dt_w[3*Ed + e];
    float dtb = dt_b[e];

    const float* up = u    + (size_t)b*Ll*Ed + e;
    const float* dp = dbc  + (size_t)b*Ll*DBC;
    const float* gp = proj + (size_t)b*Ll*TWO_E + Ed + e;
    size_t ybase = (size_t)b*Ll*Ed + e;

    float h = 0.f;
    for (int t0 = 0; t0 < Ll; t0 += 4) {
        float p[4], uq[4];
        #pragma unroll
        for (int q = 0; q < 4; q++) {
            int t = t0 + q;
            const float* dr = dp + t*DBC;
            float4 d4 = *(const float4*)dr;
            float xdt = d4.x*w0 + d4.y*w1 + d4.z*w2 + d4.w*w3 + dtb;
            float dtv = (xdt > 20.f) ? xdt : log1pf(__expf(xdt));
            float uv = up[(size_t)t*Ed];
            float bt = dr[Rr + n];
            float ct = dr[Rr + Nst + n];
            h = h*__expf(dtv*Ac) + (dtv*uv)*bt;
            p[q] = h*ct;
            uq[q] = uv;
        }
        #pragma unroll
        for (int q = 0; q < 4; q++) {
            p[q] += __shfl_xor_sync(0xffffffffu, p[q], 8);
            p[q] += __shfl_xor_sync(0xffffffffu, p[q], 4);
            p[q] += __shfl_xor_sync(0xffffffffu, p[q], 2);
            p[q] += __shfl_xor_sync(0xffffffffu, p[q], 1);
        }
        if (n == 0) {
            #pragma unroll
            for (int q = 0; q < 4; q++) {
                int t = t0 + q;
                float g = gp[(size_t)t*TWO_E];
                float y = (p[q] + uq[q]*Dc) / (1.f + __expf(-g));
                ys[ybase + (size_t)t*Ed] = __float2half(y);
            }
        }
    }
}

// ======================= launch ==============================================
extern "C" void kernel_launch(void* const* d_in, const int* in_sizes, int n_in,
                              void* d_out, int out_size)
{
    const int*   ids     = (const int*)  d_in[0];
    const float* tok_emb = (const float*)d_in[1];
    const float* pos_emb = (const float*)d_in[2];
    const float* ln_w    = (const float*)d_in[3];
    const float* ln_b    = (const float*)d_in[4];
    const float* in_w    = (const float*)d_in[5];
    const float* in_b    = (const float*)d_in[6];
    const float* conv_w  = (const float*)d_in[7];
    const float* conv_b  = (const float*)d_in[8];
    const float* xproj_w = (const float*)d_in[9];
    const float* dt_w    = (const float*)d_in[10];
    const float* dt_b    = (const float*)d_in[11];
    const float* A_log   = (const float*)d_in[12];
    const float* Dv      = (const float*)d_in[13];
    const float* out_w   = (const float*)d_in[14];
    const float* out_b   = (const float*)d_in[15];
    const float* frac_w  = (const float*)d_in[16];
    const float* frac_b  = (const float*)d_in[17];
    const float* fln_w   = (const float*)d_in[18];
    const float* fln_b   = (const float*)d_in[19];

    float *hs, *proj, *u, *dbc, *acc;
    __half *wi, *wo, *wf, *xq, *hq, *ybq;
    cudaGetSymbolAddress((void**)&hs,   g_hs);
    cudaGetSymbolAddress((void**)&proj, g_proj);
    cudaGetSymbolAddress((void**)&u,    g_u);
    cudaGetSymbolAddress((void**)&dbc,  g_dbc);
    cudaGetSymbolAddress((void**)&acc,  g_acc);
    cudaGetSymbolAddress((void**)&wi,   g_wi);
    cudaGetSymbolAddress((void**)&wo,   g_wo);
    cudaGetSymbolAddress((void**)&wf,   g_wf);
    cudaGetSymbolAddress((void**)&xq,   g_xq);
    cudaGetSymbolAddress((void**)&hq,   g_hq);
    cudaGetSymbolAddress((void**)&ybq,  g_ybq);

    cudaFuncSetAttribute(h_gemm<0,0,0,1,0>, cudaFuncAttributeMaxDynamicSharedMemorySize, HSMEM);
    cudaFuncSetAttribute(h_gemm<0,0,1,1,1>, cudaFuncAttributeMaxDynamicSharedMemorySize, HSMEM);
    cudaFuncSetAttribute(h_gemm<1,0,0,0,1>, cudaFuncAttributeMaxDynamicSharedMemorySize, HSMEM);
    cudaFuncSetAttribute(h_gemm<1,0,0,1,0>, cudaFuncAttributeMaxDynamicSharedMemorySize, HSMEM);
    cudaFuncSetAttribute(h_gemm<1,1,0,1,0>, cudaFuncAttributeMaxDynamicSharedMemorySize, HSMEM);

    // weight transpose -> fp16 [N,K]
    wtrans<<<dim3(TWO_E/32, Hd/32, NLY), dim3(32,8)>>>(in_w, wi, Hd, TWO_E);
    wtrans<<<dim3(Hd/32, Ed/32, NLY),    dim3(32,8)>>>(out_w, wo, Ed, Hd);
    wtrans<<<dim3(Hd/32, Hd/32, NLY*Cc), dim3(32,8)>>>(frac_w, wf, Hd, Hd);

    embed_kernel<<<(Mrows*Hd + 255)/256, 256>>>(ids, tok_emb, pos_emb, hs);

    for (int l = 0; l < NLY; l++) {
        // x = LN(hs [+acc/6]) -> fp16
        if (l == 0)
            ln_fused<0,1><<<Mrows, 256>>>(hs, nullptr,
                ln_w + (size_t)l*Hd, ln_b + (size_t)l*Hd, nullptr, xq);
        else
            ln_fused<1,1><<<Mrows, 256>>>(hs, acc,
                ln_w + (size_t)l*Hd, ln_b + (size_t)l*Hd, nullptr, xq);

        // proj = x @ in_w + in_b (fp32)
        h_gemm<0,0,0,1,0><<<dim3(TWO_E/128, Mrows/128), 128, HSMEM>>>(
            xq, wi + (size_t)l*TWO_E*Hd, in_b + (size_t)l*TWO_E, nullptr,
            proj, nullptr, Mrows, Hd, TWO_E);

        conv_silu<<<(Mrows*Ed + 255)/256, 256>>>(
            proj, conv_w + (size_t)l*Ed*Kc, conv_b + (size_t)l*Ed, u);

        xproj_kernel<<<Mrows/8, 256>>>(u, xproj_w + (size_t)l*Ed*DBC, dbc);

        // scan -> ys fp16 (into xq)
        scan_kernel<<<192, 256>>>(u, dbc, proj,
            dt_w + (size_t)l*Rr*Ed, dt_b + (size_t)l*Ed,
            A_log + (size_t)l*Ed*Nst, Dv + (size_t)l*Ed, xq);

        // hs = ys @ out_w + out_b + hs (fp32) ; also hq = fp16(hs)
        h_gemm<0,0,1,1,1><<<dim3(Hd/128, Mrows/128), 128, HSMEM>>>(
            xq, wo + (size_t)l*Hd*Ed, out_b + (size_t)l*Hd, hs,
            hs, hq, Mrows, Ed, Hd);

        // fractal: acc = sum_i silu^3(hs)
        for (int i = 0; i < Cc; i++) {
            const __half* fw = wf + ((size_t)l*Cc + i)*Hd*Hd;
            const float* fb = frac_b + ((size_t)l*Cc + i)*Hd;
            h_gemm<1,0,0,0,1><<<dim3(Hd/128, Mrows/128), 128, HSMEM>>>(
                hq, fw, fb, nullptr, nullptr, ybq, Mrows, Hd, Hd);
            h_gemm<1,0,0,0,1><<<dim3(Hd/128, Mrows/128), 128, HSMEM>>>(
                ybq, fw, fb, nullptr, nullptr, xq, Mrows, Hd, Hd);
            if (i == 0)
                h_gemm<1,0,0,1,0><<<dim3(Hd/128, Mrows/128), 128, HSMEM>>>(
                    xq, fw, fb, nullptr, acc, nullptr, Mrows, Hd, Hd);
            else
                h_gemm<1,1,0,1,0><<<dim3(Hd/128, Mrows/128), 128, HSMEM>>>(
                    xq, fw, fb, nullptr, acc, nullptr, Mrows, Hd, Hd);
        }
    }

    // final: hs += acc/6 ; out = LN(hs)
    ln_fused<1,0><<<Mrows, 256>>>(hs, acc, fln_w, fln_b, (float*)d_out, nullptr);
}